// round 2
// baseline (speedup 1.0000x reference)
#include <cuda_runtime.h>
#include <math.h>

#define NF   48
#define NM   51
#define KK   49
#define IMG  256
#define NB   16
#define TABN 2049
#define AS   72   // a-tile smem row stride
#define XS   80   // x-tile smem row stride

typedef unsigned long long u64;

// ---- device scratch (static globals: allowed) ----
__device__ __align__(16) float g_w2[NF * 56];   // packed weight pairs, rows of 8 (w0..w6,0)
__device__ __align__(16) float g_wr2[NF * 56];  // doubly-reversed packed pairs for conv^T
__device__ float2 g_tab[NF][TABN];              // (value, delta) per filter
__device__ float  g_r[NB * IMG * IMG];          // residual r
__device__ float  g_partial[NB * 16];           // per-tile sum(r^2)
__device__ float  g_scale[NB];                  // per-batch prox scale

// f32x2 packed helpers
__device__ __forceinline__ void fma2(u64& acc, u64 a, u64 b) {
    asm("fma.rn.f32x2 %0, %1, %2, %0;" : "+l"(acc) : "l"(a), "l"(b));
}
__device__ __forceinline__ u64 pk(float lo, float hi) {
    u64 r; asm("mov.b64 %0, {%1, %2};" : "=l"(r) : "f"(lo), "f"(hi)); return r;
}
__device__ __forceinline__ float2 upk(u64 v) {
    float2 r; asm("mov.b64 {%0, %1}, %2;" : "=f"(r.x), "=f"(r.y) : "l"(v)); return r;
}

// ---------------- K1: normalize conv weights + build packed pair tables ----------------
__global__ void prep_kernel(const float* __restrict__ cw, const float* __restrict__ sf) {
    int f = threadIdx.x;
    if (f >= NF) return;
    float wn[KK];
    float mean = 0.f;
    #pragma unroll
    for (int i = 0; i < KK; i++) mean += cw[f * KK + i];
    mean *= (1.f / 49.f);
    float ss = 0.f;
    #pragma unroll
    for (int i = 0; i < KK; i++) { float d = cw[f * KK + i] - mean; ss += d * d; }
    float s = sf[f] / (sqrtf(ss) + 1e-12f);
    #pragma unroll
    for (int i = 0; i < KK; i++) wn[i] = (cw[f * KK + i] - mean) * s;
    #pragma unroll
    for (int p = 0; p < 7; p++) {
        #pragma unroll
        for (int q = 0; q < 7; q++) {
            g_w2[f * 56 + p * 8 + q]  = wn[p * 7 + q];
            g_wr2[f * 56 + p * 8 + q] = wn[(6 - p) * 7 + (6 - q)];
        }
        g_w2[f * 56 + p * 8 + 7]  = 0.f;
        g_wr2[f * 56 + p * 8 + 7] = 0.f;
    }
}

// ---------------- K2: build per-filter RBF lookup table ----------------
__global__ void table_kernel(const float* __restrict__ rbw, const float* __restrict__ rbc) {
    __shared__ float wsh[NM], csh[NM];
    __shared__ float tsh[TABN];
    int f = blockIdx.x;
    int tid = threadIdx.x;
    if (tid < NM) { wsh[tid] = rbw[f * NM + tid]; csh[tid] = rbc[tid]; }
    __syncthreads();
    for (int k = tid; k < TABN; k += blockDim.x) {
        float z = -16.f + (float)k * (1.f / 64.f);
        float acc = 0.f;
        #pragma unroll
        for (int m = 0; m < NM; m++) {
            float d = z - csh[m];
            acc += wsh[m] * __expf(-0.01f * d * d);
        }
        tsh[k] = acc;
    }
    __syncthreads();
    for (int k = tid; k < TABN; k += blockDim.x) {
        float v = tsh[k];
        float dl = (k < TABN - 1) ? (tsh[k + 1] - v) : 0.f;
        g_tab[f][k] = make_float2(v, dl);
    }
}

// ---------------- K3: fused conv -> RBF -> conv^T -> residual (f32x2 packed) ----------------
__global__ void __launch_bounds__(256, 2)
main_kernel(const float* __restrict__ input, const float* __restrict__ net_input) {
    __shared__ __align__(16) float xs[76 * XS];   // x halo, rows -6..69, col idx = c+6, 80 wide
    __shared__ __align__(16) float as_[70 * AS];  // a tile, idx = (r+3, c+3)
    __shared__ float red[8];

    int blk  = blockIdx.x;
    int b    = blk >> 4;
    int tile = blk & 15;
    int ty0  = (tile >> 2) << 6;
    int tx0  = (tile & 3) << 6;
    int tid  = threadIdx.x;

    const float* ibase = input + b * IMG * IMG;

    // load x halo (76 rows x 80 cols) with symmetric reflection
    for (int idx = tid; idx < 76 * 80; idx += 256) {
        int ri = idx / 80, ci = idx - ri * 80;
        int gy = ty0 + ri - 6;
        int gx = tx0 + ci - 6;
        gy = (gy < 0) ? (-1 - gy) : ((gy >= IMG) ? (2 * IMG - 1 - gy) : gy);
        gx = (gx < 0) ? (-1 - gx) : ((gx >= IMG) ? (2 * IMG - 1 - gx) : gx);
        xs[ri * XS + ci] = ibase[gy * IMG + gx];
    }

    // phase-A mapping: 252 threads x (5 rows x 4 cols) of the 70x70 a-region
    bool actA = tid < 252;
    int rg = tid / 18, cg = tid - rg * 18;
    int r0 = -3 + 5 * rg;
    int c0 = -3 + 4 * cg;

    // phase-B mapping: 4x4 output block per thread
    int tyq = tid >> 4, txq = tid & 15;
    int ob = tyq << 2, oc = txq << 2;

    u64 oacc2[16];
    #pragma unroll
    for (int i = 0; i < 16; i++) oacc2[i] = 0ULL;

    __syncthreads();

    #pragma unroll 1
    for (int f = 0; f < NF; f++) {
        const float* wbase  = g_w2  + f * 56;
        const float* wrbase = g_wr2 + f * 56;

        float aout[20];
        if (actA) {
            u64 acc2[20];
            #pragma unroll
            for (int i = 0; i < 20; i++) acc2[i] = 0ULL;

            #pragma unroll
            for (int wr = 0; wr < 11; wr++) {
                const float* xp = xs + (r0 + 3 + wr) * XS + 4 * cg;
                float4 v0 = *(const float4*)xp;
                float4 v1 = *(const float4*)(xp + 4);
                float4 v2 = *(const float4*)(xp + 8);
                float xr[12] = {v0.x, v0.y, v0.z, v0.w, v1.x, v1.y, v1.z, v1.w,
                                v2.x, v2.y, v2.z, v2.w};
                u64 P[10];
                #pragma unroll
                for (int k = 0; k < 10; k++) P[k] = pk(xr[k], xr[k + 1]);
                #pragma unroll
                for (int i = 0; i < 5; i++) {
                    int p = wr - i;
                    if (p >= 0 && p < 7) {
                        ulonglong2 wA = *(const ulonglong2*)(wbase + p * 8);
                        ulonglong2 wB = *(const ulonglong2*)(wbase + p * 8 + 4);
                        #pragma unroll
                        for (int j = 0; j < 4; j++) {
                            fma2(acc2[i * 4 + j], wA.x, P[j]);
                            fma2(acc2[i * 4 + j], wA.y, P[j + 2]);
                            fma2(acc2[i * 4 + j], wB.x, P[j + 4]);
                            fma2(acc2[i * 4 + j], wB.y, P[j + 6]);
                        }
                    }
                }
            }
            // RBF via table lerp; zero outside the image (conv^T zero-pads a)
            const float2* tb = g_tab[f];
            #pragma unroll
            for (int i = 0; i < 5; i++) {
                int gr = ty0 + r0 + i;
                bool rok = (gr >= 0) && (gr < IMG);
                #pragma unroll
                for (int j = 0; j < 4; j++) {
                    float2 zz = upk(acc2[i * 4 + j]);
                    float z = zz.x + zz.y;
                    float t = (z + 16.f) * 64.f;
                    t = fminf(fmaxf(t, 0.f), 2047.99f);
                    int ix = (int)t;
                    float fr = t - (float)ix;
                    float2 tv = __ldg(tb + ix);
                    float a = tv.x + fr * tv.y;
                    int gc = tx0 + c0 + j;
                    if (!rok || gc < 0 || gc >= IMG) a = 0.f;
                    aout[i * 4 + j] = a;
                }
            }
        }
        __syncthreads();   // previous phase-B reads of as_ complete
        if (actA) {
            #pragma unroll
            for (int i = 0; i < 5; i++) {
                float4 st = make_float4(aout[i * 4], aout[i * 4 + 1],
                                        aout[i * 4 + 2], aout[i * 4 + 3]);
                *(float4*)(as_ + (r0 + i + 3) * AS + (c0 + 3)) = st;
            }
        }
        __syncthreads();   // a tile ready

        // conv^T as correlation with doubly-reversed packed weights
        #pragma unroll
        for (int wrb = 0; wrb < 10; wrb++) {
            const float* ap = as_ + (ob + wrb) * AS + oc;
            float4 u0 = *(const float4*)ap;
            float4 u1 = *(const float4*)(ap + 4);
            float4 u2 = *(const float4*)(ap + 8);
            float ar[12] = {u0.x, u0.y, u0.z, u0.w, u1.x, u1.y, u1.z, u1.w,
                            u2.x, u2.y, u2.z, u2.w};
            u64 P[10];
            #pragma unroll
            for (int k = 0; k < 10; k++) P[k] = pk(ar[k], ar[k + 1]);
            #pragma unroll
            for (int i = 0; i < 4; i++) {
                int p = wrb - i;
                if (p >= 0 && p < 7) {
                    ulonglong2 wA = *(const ulonglong2*)(wrbase + p * 8);
                    ulonglong2 wB = *(const ulonglong2*)(wrbase + p * 8 + 4);
                    #pragma unroll
                    for (int j = 0; j < 4; j++) {
                        fma2(oacc2[i * 4 + j], wA.x, P[j]);
                        fma2(oacc2[i * 4 + j], wA.y, P[j + 2]);
                        fma2(oacc2[i * 4 + j], wB.x, P[j + 4]);
                        fma2(oacc2[i * 4 + j], wB.y, P[j + 6]);
                    }
                }
            }
        }
    }

    // epilogue: r = input - convt - net_input ; per-block sum(r^2)
    const float* nbase = net_input + b * IMG * IMG;
    float* rbase = g_r + b * IMG * IMG;
    float ss = 0.f;
    #pragma unroll
    for (int i = 0; i < 4; i++) {
        int gy = ty0 + ob + i;
        int go = gy * IMG + tx0 + oc;
        float4 iv = *(const float4*)(ibase + go);
        float4 nv = *(const float4*)(nbase + go);
        float2 c0v = upk(oacc2[i * 4 + 0]);
        float2 c1v = upk(oacc2[i * 4 + 1]);
        float2 c2v = upk(oacc2[i * 4 + 2]);
        float2 c3v = upk(oacc2[i * 4 + 3]);
        float4 rv;
        rv.x = iv.x - (c0v.x + c0v.y) - nv.x;
        rv.y = iv.y - (c1v.x + c1v.y) - nv.y;
        rv.z = iv.z - (c2v.x + c2v.y) - nv.z;
        rv.w = iv.w - (c3v.x + c3v.y) - nv.w;
        *(float4*)(rbase + go) = rv;
        ss += rv.x * rv.x + rv.y * rv.y + rv.z * rv.z + rv.w * rv.w;
    }
    // deterministic block reduction
    #pragma unroll
    for (int o = 16; o > 0; o >>= 1) ss += __shfl_down_sync(0xffffffffu, ss, o);
    if ((tid & 31) == 0) red[tid >> 5] = ss;
    __syncthreads();
    if (tid == 0) {
        float s = 0.f;
        #pragma unroll
        for (int w = 0; w < 8; w++) s += red[w];
        g_partial[blk] = s;
    }
}

// ---------------- K4a: per-batch prox scale ----------------
__global__ void scale_kernel(const float* __restrict__ stdn, const float* __restrict__ alpha) {
    int b = blockIdx.x;
    if (threadIdx.x == 0) {
        float s = 0.f;
        #pragma unroll
        for (int t = 0; t < 16; t++) s += g_partial[b * 16 + t];
        float nr = sqrtf(s);
        float k = expf(alpha[0]) * stdn[b] * 256.f;
        g_scale[b] = fminf(1.f, k / (nr + 1e-12f));
    }
}

// ---------------- K4b: out = net_input + r * scale[b] ----------------
__global__ void final_kernel(const float* __restrict__ net_input, float* __restrict__ out) {
    int v = blockIdx.x * blockDim.x + threadIdx.x;
    if (v >= NB * IMG * IMG / 4) return;
    int b = v >> 14;
    float sc = g_scale[b];
    float4 rr = ((const float4*)g_r)[v];
    float4 nn = ((const float4*)net_input)[v];
    float4 o;
    o.x = nn.x + rr.x * sc;
    o.y = nn.y + rr.y * sc;
    o.z = nn.z + rr.z * sc;
    o.w = nn.w + rr.w * sc;
    ((float4*)out)[v] = o;
}

extern "C" void kernel_launch(void* const* d_in, const int* in_sizes, int n_in,
                              void* d_out, int out_size) {
    const float* input     = (const float*)d_in[0];
    const float* stdn      = (const float*)d_in[1];
    const float* net_input = (const float*)d_in[3];
    const float* cw        = (const float*)d_in[4];
    const float* sf        = (const float*)d_in[5];
    const float* alpha     = (const float*)d_in[6];
    const float* rbw       = (const float*)d_in[7];
    const float* rbc       = (const float*)d_in[8];
    float* out = (float*)d_out;

    prep_kernel<<<1, 64>>>(cw, sf);
    table_kernel<<<NF, 256>>>(rbw, rbc);
    main_kernel<<<256, 256>>>(input, net_input);
    scale_kernel<<<NB, 32>>>(stdn, alpha);
    final_kernel<<<1024, 256>>>(net_input, out);
}

// round 3
// speedup vs baseline: 1.0001x; 1.0001x over previous
#include <cuda_runtime.h>
#include <math.h>

#define NF   48
#define NM   51
#define KK   49
#define IMG  256
#define NB   16
#define TABN 2049
#define AS   72   // a-tile smem row stride
#define XS   80   // x-tile smem row stride

typedef unsigned long long u64;

// ---- device scratch (static globals: allowed) ----
__device__ __align__(16) float g_w2[NF * 56];   // packed weight pairs, rows of 8 (w0..w6,0)
__device__ __align__(16) float g_wr2[NF * 56];  // doubly-reversed packed pairs for conv^T
__device__ float2 g_tab[NF][TABN];              // (value, delta) per filter
__device__ float  g_r[NB * IMG * IMG];          // residual r
__device__ float  g_partial[NB * 16];           // per-tile sum(r^2)
__device__ float  g_scale[NB];                  // per-batch prox scale

// f32x2 packed helpers
__device__ __forceinline__ void fma2(u64& acc, u64 a, u64 b) {
    asm("fma.rn.f32x2 %0, %1, %2, %0;" : "+l"(acc) : "l"(a), "l"(b));
}
__device__ __forceinline__ u64 pk(float lo, float hi) {
    u64 r; asm("mov.b64 %0, {%1, %2};" : "=l"(r) : "f"(lo), "f"(hi)); return r;
}
__device__ __forceinline__ float2 upk(u64 v) {
    float2 r; asm("mov.b64 {%0, %1}, %2;" : "=f"(r.x), "=f"(r.y) : "l"(v)); return r;
}

// ---------------- K1: normalize conv weights + build packed pair tables ----------------
__global__ void prep_kernel(const float* __restrict__ cw, const float* __restrict__ sf) {
    int f = threadIdx.x;
    if (f >= NF) return;
    float wn[KK];
    float mean = 0.f;
    #pragma unroll
    for (int i = 0; i < KK; i++) mean += cw[f * KK + i];
    mean *= (1.f / 49.f);
    float ss = 0.f;
    #pragma unroll
    for (int i = 0; i < KK; i++) { float d = cw[f * KK + i] - mean; ss += d * d; }
    float s = sf[f] / (sqrtf(ss) + 1e-12f);
    #pragma unroll
    for (int i = 0; i < KK; i++) wn[i] = (cw[f * KK + i] - mean) * s;
    #pragma unroll
    for (int p = 0; p < 7; p++) {
        #pragma unroll
        for (int q = 0; q < 7; q++) {
            g_w2[f * 56 + p * 8 + q]  = wn[p * 7 + q];
            g_wr2[f * 56 + p * 8 + q] = wn[(6 - p) * 7 + (6 - q)];
        }
        g_w2[f * 56 + p * 8 + 7]  = 0.f;
        g_wr2[f * 56 + p * 8 + 7] = 0.f;
    }
}

// ---------------- K2: build per-filter RBF lookup table ----------------
__global__ void table_kernel(const float* __restrict__ rbw, const float* __restrict__ rbc) {
    __shared__ float wsh[NM], csh[NM];
    __shared__ float tsh[TABN];
    int f = blockIdx.x;
    int tid = threadIdx.x;
    if (tid < NM) { wsh[tid] = rbw[f * NM + tid]; csh[tid] = rbc[tid]; }
    __syncthreads();
    for (int k = tid; k < TABN; k += blockDim.x) {
        float z = -16.f + (float)k * (1.f / 64.f);
        float acc = 0.f;
        #pragma unroll
        for (int m = 0; m < NM; m++) {
            float d = z - csh[m];
            acc += wsh[m] * __expf(-0.01f * d * d);
        }
        tsh[k] = acc;
    }
    __syncthreads();
    for (int k = tid; k < TABN; k += blockDim.x) {
        float v = tsh[k];
        float dl = (k < TABN - 1) ? (tsh[k + 1] - v) : 0.f;
        g_tab[f][k] = make_float2(v, dl);
    }
}

// ---------------- K3: fused conv -> RBF -> conv^T -> residual (f32x2 packed) ----------------
__global__ void __launch_bounds__(256, 2)
main_kernel(const float* __restrict__ input, const float* __restrict__ net_input) {
    __shared__ __align__(16) float xs[76 * XS];   // x halo, rows -6..69, col idx = c+6, 80 wide
    __shared__ __align__(16) float as_[70 * AS];  // a tile, idx = (r+3, c+3)
    __shared__ float red[8];

    int blk  = blockIdx.x;
    int b    = blk >> 4;
    int tile = blk & 15;
    int ty0  = (tile >> 2) << 6;
    int tx0  = (tile & 3) << 6;
    int tid  = threadIdx.x;

    const float* ibase = input + b * IMG * IMG;

    // load x halo (76 rows x 80 cols) with symmetric reflection
    for (int idx = tid; idx < 76 * 80; idx += 256) {
        int ri = idx / 80, ci = idx - ri * 80;
        int gy = ty0 + ri - 6;
        int gx = tx0 + ci - 6;
        gy = (gy < 0) ? (-1 - gy) : ((gy >= IMG) ? (2 * IMG - 1 - gy) : gy);
        gx = (gx < 0) ? (-1 - gx) : ((gx >= IMG) ? (2 * IMG - 1 - gx) : gx);
        xs[ri * XS + ci] = ibase[gy * IMG + gx];
    }

    // phase-A mapping: 252 threads x (5 rows x 4 cols) of the 70x70 a-region
    bool actA = tid < 252;
    int rg = tid / 18, cg = tid - rg * 18;
    int r0 = -3 + 5 * rg;
    int c0 = -3 + 4 * cg;

    // phase-B mapping: 4x4 output block per thread
    int tyq = tid >> 4, txq = tid & 15;
    int ob = tyq << 2, oc = txq << 2;

    u64 oacc2[16];
    #pragma unroll
    for (int i = 0; i < 16; i++) oacc2[i] = 0ULL;

    __syncthreads();

    #pragma unroll 1
    for (int f = 0; f < NF; f++) {
        const float* wbase  = g_w2  + f * 56;
        const float* wrbase = g_wr2 + f * 56;

        float aout[20];
        if (actA) {
            u64 acc2[20];
            #pragma unroll
            for (int i = 0; i < 20; i++) acc2[i] = 0ULL;

            #pragma unroll
            for (int wr = 0; wr < 11; wr++) {
                const float* xp = xs + (r0 + 3 + wr) * XS + 4 * cg;
                float4 v0 = *(const float4*)xp;
                float4 v1 = *(const float4*)(xp + 4);
                float4 v2 = *(const float4*)(xp + 8);
                float xr[12] = {v0.x, v0.y, v0.z, v0.w, v1.x, v1.y, v1.z, v1.w,
                                v2.x, v2.y, v2.z, v2.w};
                u64 P[10];
                #pragma unroll
                for (int k = 0; k < 10; k++) P[k] = pk(xr[k], xr[k + 1]);
                #pragma unroll
                for (int i = 0; i < 5; i++) {
                    int p = wr - i;
                    if (p >= 0 && p < 7) {
                        ulonglong2 wA = *(const ulonglong2*)(wbase + p * 8);
                        ulonglong2 wB = *(const ulonglong2*)(wbase + p * 8 + 4);
                        #pragma unroll
                        for (int j = 0; j < 4; j++) {
                            fma2(acc2[i * 4 + j], wA.x, P[j]);
                            fma2(acc2[i * 4 + j], wA.y, P[j + 2]);
                            fma2(acc2[i * 4 + j], wB.x, P[j + 4]);
                            fma2(acc2[i * 4 + j], wB.y, P[j + 6]);
                        }
                    }
                }
            }
            // RBF via table lerp; zero outside the image (conv^T zero-pads a)
            const float2* tb = g_tab[f];
            #pragma unroll
            for (int i = 0; i < 5; i++) {
                int gr = ty0 + r0 + i;
                bool rok = (gr >= 0) && (gr < IMG);
                #pragma unroll
                for (int j = 0; j < 4; j++) {
                    float2 zz = upk(acc2[i * 4 + j]);
                    float z = zz.x + zz.y;
                    float t = (z + 16.f) * 64.f;
                    t = fminf(fmaxf(t, 0.f), 2047.99f);
                    int ix = (int)t;
                    float fr = t - (float)ix;
                    float2 tv = __ldg(tb + ix);
                    float a = tv.x + fr * tv.y;
                    int gc = tx0 + c0 + j;
                    if (!rok || gc < 0 || gc >= IMG) a = 0.f;
                    aout[i * 4 + j] = a;
                }
            }
        }
        __syncthreads();   // previous phase-B reads of as_ complete
        if (actA) {
            #pragma unroll
            for (int i = 0; i < 5; i++) {
                float4 st = make_float4(aout[i * 4], aout[i * 4 + 1],
                                        aout[i * 4 + 2], aout[i * 4 + 3]);
                *(float4*)(as_ + (r0 + i + 3) * AS + (c0 + 3)) = st;
            }
        }
        __syncthreads();   // a tile ready

        // conv^T as correlation with doubly-reversed packed weights
        #pragma unroll
        for (int wrb = 0; wrb < 10; wrb++) {
            const float* ap = as_ + (ob + wrb) * AS + oc;
            float4 u0 = *(const float4*)ap;
            float4 u1 = *(const float4*)(ap + 4);
            float4 u2 = *(const float4*)(ap + 8);
            float ar[12] = {u0.x, u0.y, u0.z, u0.w, u1.x, u1.y, u1.z, u1.w,
                            u2.x, u2.y, u2.z, u2.w};
            u64 P[10];
            #pragma unroll
            for (int k = 0; k < 10; k++) P[k] = pk(ar[k], ar[k + 1]);
            #pragma unroll
            for (int i = 0; i < 4; i++) {
                int p = wrb - i;
                if (p >= 0 && p < 7) {
                    ulonglong2 wA = *(const ulonglong2*)(wrbase + p * 8);
                    ulonglong2 wB = *(const ulonglong2*)(wrbase + p * 8 + 4);
                    #pragma unroll
                    for (int j = 0; j < 4; j++) {
                        fma2(oacc2[i * 4 + j], wA.x, P[j]);
                        fma2(oacc2[i * 4 + j], wA.y, P[j + 2]);
                        fma2(oacc2[i * 4 + j], wB.x, P[j + 4]);
                        fma2(oacc2[i * 4 + j], wB.y, P[j + 6]);
                    }
                }
            }
        }
    }

    // epilogue: r = input - convt - net_input ; per-block sum(r^2)
    const float* nbase = net_input + b * IMG * IMG;
    float* rbase = g_r + b * IMG * IMG;
    float ss = 0.f;
    #pragma unroll
    for (int i = 0; i < 4; i++) {
        int gy = ty0 + ob + i;
        int go = gy * IMG + tx0 + oc;
        float4 iv = *(const float4*)(ibase + go);
        float4 nv = *(const float4*)(nbase + go);
        float2 c0v = upk(oacc2[i * 4 + 0]);
        float2 c1v = upk(oacc2[i * 4 + 1]);
        float2 c2v = upk(oacc2[i * 4 + 2]);
        float2 c3v = upk(oacc2[i * 4 + 3]);
        float4 rv;
        rv.x = iv.x - (c0v.x + c0v.y) - nv.x;
        rv.y = iv.y - (c1v.x + c1v.y) - nv.y;
        rv.z = iv.z - (c2v.x + c2v.y) - nv.z;
        rv.w = iv.w - (c3v.x + c3v.y) - nv.w;
        *(float4*)(rbase + go) = rv;
        ss += rv.x * rv.x + rv.y * rv.y + rv.z * rv.z + rv.w * rv.w;
    }
    // deterministic block reduction
    #pragma unroll
    for (int o = 16; o > 0; o >>= 1) ss += __shfl_down_sync(0xffffffffu, ss, o);
    if ((tid & 31) == 0) red[tid >> 5] = ss;
    __syncthreads();
    if (tid == 0) {
        float s = 0.f;
        #pragma unroll
        for (int w = 0; w < 8; w++) s += red[w];
        g_partial[blk] = s;
    }
}

// ---------------- K4a: per-batch prox scale ----------------
__global__ void scale_kernel(const float* __restrict__ stdn, const float* __restrict__ alpha) {
    int b = blockIdx.x;
    if (threadIdx.x == 0) {
        float s = 0.f;
        #pragma unroll
        for (int t = 0; t < 16; t++) s += g_partial[b * 16 + t];
        float nr = sqrtf(s);
        float k = expf(alpha[0]) * stdn[b] * 256.f;
        g_scale[b] = fminf(1.f, k / (nr + 1e-12f));
    }
}

// ---------------- K4b: out = net_input + r * scale[b] ----------------
__global__ void final_kernel(const float* __restrict__ net_input, float* __restrict__ out) {
    int v = blockIdx.x * blockDim.x + threadIdx.x;
    if (v >= NB * IMG * IMG / 4) return;
    int b = v >> 14;
    float sc = g_scale[b];
    float4 rr = ((const float4*)g_r)[v];
    float4 nn = ((const float4*)net_input)[v];
    float4 o;
    o.x = nn.x + rr.x * sc;
    o.y = nn.y + rr.y * sc;
    o.z = nn.z + rr.z * sc;
    o.w = nn.w + rr.w * sc;
    ((float4*)out)[v] = o;
}

extern "C" void kernel_launch(void* const* d_in, const int* in_sizes, int n_in,
                              void* d_out, int out_size) {
    const float* input     = (const float*)d_in[0];
    const float* stdn      = (const float*)d_in[1];
    const float* net_input = (const float*)d_in[3];
    const float* cw        = (const float*)d_in[4];
    const float* sf        = (const float*)d_in[5];
    const float* alpha     = (const float*)d_in[6];
    const float* rbw       = (const float*)d_in[7];
    const float* rbc       = (const float*)d_in[8];
    float* out = (float*)d_out;

    prep_kernel<<<1, 64>>>(cw, sf);
    table_kernel<<<NF, 256>>>(rbw, rbc);
    main_kernel<<<256, 256>>>(input, net_input);
    scale_kernel<<<NB, 32>>>(stdn, alpha);
    final_kernel<<<1024, 256>>>(net_input, out);
}

// round 4
// speedup vs baseline: 1.2956x; 1.2955x over previous
#include <cuda_runtime.h>
#include <cuda_fp16.h>
#include <math.h>
#include <stdint.h>

#define NF   48
#define NM   51
#define IMG  256
#define NB   16
#define TABN 2049
#define XS   80   // xs half stride
#define AS   72   // a half stride

// ---- device scratch ----
__device__ __align__(16) uint32_t g_wb[NF * 52];   // half2-broadcast weights
__device__ __align__(16) uint32_t g_wbr[NF * 52];  // reversed broadcast weights
__device__ float2 g_tab[NF * TABN];
__device__ float  g_r[NB * IMG * IMG];
__device__ float  g_partial[NB * 16];
__device__ float  g_scale[NB];

__device__ __forceinline__ half2 u2h(uint32_t u) { return *reinterpret_cast<half2*>(&u); }

// ---------------- K1: normalize weights, build half2 broadcast tables ----------------
__global__ void prep_kernel(const float* __restrict__ cw, const float* __restrict__ sf) {
    int f = threadIdx.x;
    if (f >= NF) return;
    float wn[49];
    float mean = 0.f;
    #pragma unroll
    for (int i = 0; i < 49; i++) mean += cw[f * 49 + i];
    mean *= (1.f / 49.f);
    float ss = 0.f;
    #pragma unroll
    for (int i = 0; i < 49; i++) { float d = cw[f * 49 + i] - mean; ss += d * d; }
    float s = sf[f] / (sqrtf(ss) + 1e-12f);
    #pragma unroll
    for (int i = 0; i < 49; i++) wn[i] = (cw[f * 49 + i] - mean) * s;
    #pragma unroll
    for (int p = 0; p < 7; p++)
        #pragma unroll
        for (int q = 0; q < 7; q++) {
            uint32_t h  = (uint32_t)__half_as_ushort(__float2half(wn[p * 7 + q]));
            uint32_t hr = (uint32_t)__half_as_ushort(__float2half(wn[(6 - p) * 7 + (6 - q)]));
            g_wb[f * 52 + p * 7 + q]  = h | (h << 16);
            g_wbr[f * 52 + p * 7 + q] = hr | (hr << 16);
        }
    #pragma unroll
    for (int i = 49; i < 52; i++) { g_wb[f * 52 + i] = 0; g_wbr[f * 52 + i] = 0; }
}

// ---------------- K2: RBF lookup table ----------------
__global__ void table_kernel(const float* __restrict__ rbw, const float* __restrict__ rbc) {
    __shared__ float wsh[NM], csh[NM];
    __shared__ float tsh[TABN];
    int f = blockIdx.x, tid = threadIdx.x;
    if (tid < NM) { wsh[tid] = rbw[f * NM + tid]; csh[tid] = rbc[tid]; }
    __syncthreads();
    for (int k = tid; k < TABN; k += blockDim.x) {
        float z = -16.f + (float)k * (1.f / 64.f);
        float acc = 0.f;
        #pragma unroll
        for (int m = 0; m < NM; m++) {
            float d = z - csh[m];
            acc += wsh[m] * __expf(-0.01f * d * d);
        }
        tsh[k] = acc;
    }
    __syncthreads();
    for (int k = tid; k < TABN; k += blockDim.x) {
        float v = tsh[k];
        float dl = (k < TABN - 1) ? (tsh[k + 1] - v) : 0.f;
        g_tab[f * TABN + k] = make_float2(v, dl);
    }
}

// ---------------- K3: fused conv -> RBF -> conv^T -> residual (HFMA2) ----------------
__global__ void __launch_bounds__(256, 2)
main_kernel(const float* __restrict__ input, const float* __restrict__ net_input) {
    __shared__ __align__(16) half xs[76 * XS];
    __shared__ __align__(16) half as_h[70 * AS];
    __shared__ float red[8];

    int blk  = blockIdx.x;
    int b    = blk >> 4;
    int tile = blk & 15;
    int ty0  = (tile >> 2) << 6;
    int tx0  = (tile & 3) << 6;
    int tid  = threadIdx.x;

    const float* ibase = input + b * IMG * IMG;

    for (int idx = tid; idx < 76 * XS; idx += 256) {
        int ri = idx / XS, ci = idx - ri * XS;
        float v = 0.f;
        if (ci < 78) {
            int gy = ty0 + ri - 6, gx = tx0 + ci - 6;
            gy = (gy < 0) ? (-1 - gy) : ((gy >= IMG) ? (2 * IMG - 1 - gy) : gy);
            gx = (gx < 0) ? (-1 - gx) : ((gx >= IMG) ? (2 * IMG - 1 - gx) : gx);
            v = ibase[gy * IMG + gx];
        }
        xs[ri * XS + ci] = __float2half(v);
    }

    bool actA = tid < 252;
    int rg = tid / 18, cg = tid - rg * 18;
    int r0 = -3 + 5 * rg;
    int c0 = -3 + 4 * cg;

    int tyq = tid >> 4, txq = tid & 15;
    int ob = tyq << 2, oc = txq << 2;

    float oacc[16];
    #pragma unroll
    for (int i = 0; i < 16; i++) oacc[i] = 0.f;

    __syncthreads();

    #pragma unroll 1
    for (int f = 0; f < NF; f++) {
        // ---- phase A: forward conv (half2) + RBF ----
        float aout[20];
        if (actA) {
            uint32_t wb[52];
            const uint4* wp = (const uint4*)(g_wb + f * 52);
            #pragma unroll
            for (int v = 0; v < 13; v++) {
                uint4 t = __ldg(wp + v);
                wb[4 * v] = t.x; wb[4 * v + 1] = t.y; wb[4 * v + 2] = t.z; wb[4 * v + 3] = t.w;
            }
            half2 za[10];
            #pragma unroll
            for (int i = 0; i < 10; i++) za[i] = __float2half2_rn(0.f);

            #pragma unroll
            for (int wr = 0; wr < 11; wr++) {
                const half* xp = xs + (r0 + 3 + wr) * XS + 4 * cg;
                half2 P[5], O[4];
                #pragma unroll
                for (int k = 0; k < 5; k++) P[k] = *(const half2*)(xp + 2 * k);
                #pragma unroll
                for (int k = 0; k < 4; k++)
                    O[k] = __halves2half2(__high2half(P[k]), __low2half(P[k + 1]));
                #pragma unroll
                for (int i = 0; i < 5; i++) {
                    int p = wr - i;
                    if (p >= 0 && p < 7) {
                        const uint32_t* w = wb + p * 7;
                        half2 a0 = za[i * 2], a1 = za[i * 2 + 1];
                        a0 = __hfma2(u2h(w[0]), P[0], a0);  a1 = __hfma2(u2h(w[0]), P[1], a1);
                        a0 = __hfma2(u2h(w[1]), O[0], a0);  a1 = __hfma2(u2h(w[1]), O[1], a1);
                        a0 = __hfma2(u2h(w[2]), P[1], a0);  a1 = __hfma2(u2h(w[2]), P[2], a1);
                        a0 = __hfma2(u2h(w[3]), O[1], a0);  a1 = __hfma2(u2h(w[3]), O[2], a1);
                        a0 = __hfma2(u2h(w[4]), P[2], a0);  a1 = __hfma2(u2h(w[4]), P[3], a1);
                        a0 = __hfma2(u2h(w[5]), O[2], a0);  a1 = __hfma2(u2h(w[5]), O[3], a1);
                        a0 = __hfma2(u2h(w[6]), P[3], a0);  a1 = __hfma2(u2h(w[6]), P[4], a1);
                        za[i * 2] = a0; za[i * 2 + 1] = a1;
                    }
                }
            }
            const float2* tb = g_tab + f * TABN;
            #pragma unroll
            for (int i = 0; i < 5; i++) {
                int gr = ty0 + r0 + i;
                bool rok = (gr >= 0) && (gr < IMG);
                float2 zl = __half22float2(za[i * 2]);
                float2 zh = __half22float2(za[i * 2 + 1]);
                float zv[4] = {zl.x, zl.y, zh.x, zh.y};
                #pragma unroll
                for (int j = 0; j < 4; j++) {
                    float t = (zv[j] + 16.f) * 64.f;
                    t = fminf(fmaxf(t, 0.f), 2047.99f);
                    int ix = (int)t;
                    float fr = t - (float)ix;
                    float2 tv = __ldg(tb + ix);
                    float a = tv.x + fr * tv.y;
                    int gc = tx0 + c0 + j;
                    if (!rok || gc < 0 || gc >= IMG) a = 0.f;
                    aout[i * 4 + j] = a;
                }
            }
        }
        __syncthreads();
        if (actA) {
            #pragma unroll
            for (int i = 0; i < 5; i++) {
                half* dst = as_h + (r0 + i + 3) * AS + 4 * cg;
                *(half2*)dst       = __floats2half2_rn(aout[i * 4], aout[i * 4 + 1]);
                *(half2*)(dst + 2) = __floats2half2_rn(aout[i * 4 + 2], aout[i * 4 + 3]);
            }
        }
        __syncthreads();

        // ---- phase B: conv^T (reversed weights, half2, per-filter fp32 fold) ----
        {
            uint32_t wb[52];
            const uint4* wp = (const uint4*)(g_wbr + f * 52);
            #pragma unroll
            for (int v = 0; v < 13; v++) {
                uint4 t = __ldg(wp + v);
                wb[4 * v] = t.x; wb[4 * v + 1] = t.y; wb[4 * v + 2] = t.z; wb[4 * v + 3] = t.w;
            }
            half2 ga[8];
            #pragma unroll
            for (int i = 0; i < 8; i++) ga[i] = __float2half2_rn(0.f);

            #pragma unroll
            for (int wrb = 0; wrb < 10; wrb++) {
                const half* ap = as_h + (ob + wrb) * AS + oc;
                half2 P[5], O[4];
                #pragma unroll
                for (int k = 0; k < 5; k++) P[k] = *(const half2*)(ap + 2 * k);
                #pragma unroll
                for (int k = 0; k < 4; k++)
                    O[k] = __halves2half2(__high2half(P[k]), __low2half(P[k + 1]));
                #pragma unroll
                for (int i = 0; i < 4; i++) {
                    int p = wrb - i;
                    if (p >= 0 && p < 7) {
                        const uint32_t* w = wb + p * 7;
                        half2 a0 = ga[i * 2], a1 = ga[i * 2 + 1];
                        a0 = __hfma2(u2h(w[0]), P[0], a0);  a1 = __hfma2(u2h(w[0]), P[1], a1);
                        a0 = __hfma2(u2h(w[1]), O[0], a0);  a1 = __hfma2(u2h(w[1]), O[1], a1);
                        a0 = __hfma2(u2h(w[2]), P[1], a0);  a1 = __hfma2(u2h(w[2]), P[2], a1);
                        a0 = __hfma2(u2h(w[3]), O[1], a0);  a1 = __hfma2(u2h(w[3]), O[2], a1);
                        a0 = __hfma2(u2h(w[4]), P[2], a0);  a1 = __hfma2(u2h(w[4]), P[3], a1);
                        a0 = __hfma2(u2h(w[5]), O[2], a0);  a1 = __hfma2(u2h(w[5]), O[3], a1);
                        a0 = __hfma2(u2h(w[6]), P[3], a0);  a1 = __hfma2(u2h(w[6]), P[4], a1);
                        ga[i * 2] = a0; ga[i * 2 + 1] = a1;
                    }
                }
            }
            #pragma unroll
            for (int i = 0; i < 4; i++) {
                float2 lo = __half22float2(ga[i * 2]);
                float2 hi = __half22float2(ga[i * 2 + 1]);
                oacc[i * 4 + 0] += lo.x; oacc[i * 4 + 1] += lo.y;
                oacc[i * 4 + 2] += hi.x; oacc[i * 4 + 3] += hi.y;
            }
        }
    }

    // epilogue: r = input - convt - net_input ; per-block sum(r^2)
    const float* nbase = net_input + b * IMG * IMG;
    float* rbase = g_r + b * IMG * IMG;
    float ss = 0.f;
    #pragma unroll
    for (int i = 0; i < 4; i++) {
        int gy = ty0 + ob + i;
        int go = gy * IMG + tx0 + oc;
        float4 iv = *(const float4*)(ibase + go);
        float4 nv = *(const float4*)(nbase + go);
        float4 rv;
        rv.x = iv.x - oacc[i * 4 + 0] - nv.x;
        rv.y = iv.y - oacc[i * 4 + 1] - nv.y;
        rv.z = iv.z - oacc[i * 4 + 2] - nv.z;
        rv.w = iv.w - oacc[i * 4 + 3] - nv.w;
        *(float4*)(rbase + go) = rv;
        ss += rv.x * rv.x + rv.y * rv.y + rv.z * rv.z + rv.w * rv.w;
    }
    #pragma unroll
    for (int o = 16; o > 0; o >>= 1) ss += __shfl_down_sync(0xffffffffu, ss, o);
    if ((tid & 31) == 0) red[tid >> 5] = ss;
    __syncthreads();
    if (tid == 0) {
        float s = 0.f;
        #pragma unroll
        for (int w = 0; w < 8; w++) s += red[w];
        g_partial[blk] = s;
    }
}

// ---------------- K4a / K4b ----------------
__global__ void scale_kernel(const float* __restrict__ stdn, const float* __restrict__ alpha) {
    int b = blockIdx.x;
    if (threadIdx.x == 0) {
        float s = 0.f;
        #pragma unroll
        for (int t = 0; t < 16; t++) s += g_partial[b * 16 + t];
        float nr = sqrtf(s);
        float k = expf(alpha[0]) * stdn[b] * 256.f;
        g_scale[b] = fminf(1.f, k / (nr + 1e-12f));
    }
}

__global__ void final_kernel(const float* __restrict__ net_input, float* __restrict__ out) {
    int v = blockIdx.x * blockDim.x + threadIdx.x;
    if (v >= NB * IMG * IMG / 4) return;
    int b = v >> 14;
    float sc = g_scale[b];
    float4 rr = ((const float4*)g_r)[v];
    float4 nn = ((const float4*)net_input)[v];
    float4 o;
    o.x = nn.x + rr.x * sc;
    o.y = nn.y + rr.y * sc;
    o.z = nn.z + rr.z * sc;
    o.w = nn.w + rr.w * sc;
    ((float4*)out)[v] = o;
}

extern "C" void kernel_launch(void* const* d_in, const int* in_sizes, int n_in,
                              void* d_out, int out_size) {
    const float* input     = (const float*)d_in[0];
    const float* stdn      = (const float*)d_in[1];
    const float* net_input = (const float*)d_in[3];
    const float* cw        = (const float*)d_in[4];
    const float* sf        = (const float*)d_in[5];
    const float* alpha     = (const float*)d_in[6];
    const float* rbw       = (const float*)d_in[7];
    const float* rbc       = (const float*)d_in[8];
    float* out = (float*)d_out;

    prep_kernel<<<1, 64>>>(cw, sf);
    table_kernel<<<NF, 256>>>(rbw, rbc);
    main_kernel<<<256, 256>>>(input, net_input);
    scale_kernel<<<NB, 32>>>(stdn, alpha);
    final_kernel<<<1024, 256>>>(net_input, out);
}